// round 2
// baseline (speedup 1.0000x reference)
#include <cuda_runtime.h>
#include <math.h>

#define N_NODES   50000
#define N_GROUPS  10000
#define N_EDGES   500000
#define N_TRIP    1000000
#define HID       128
#define NR        6
#define NS        7
#define FEAT      48      // 42 sbf-accum + 6 rbf
#define EPSF      1e-6f
#define CUTOFF    5.0f
#define PI_F      3.14159265358979323846f

// scratch: per-edge feature row: [0..41] = accumulated sbf (l*6+n), [42..47] = rbf
__device__ __align__(16) float g_feat[(size_t)N_EDGES * FEAT];

// ---------------------------------------------------------------------------
// Kernel 1: per-edge RBF + zero the sbf accumulator portion of the row
// ---------------------------------------------------------------------------
__global__ void rbf_kernel(const float* __restrict__ node_pos,
                           const int*   __restrict__ edge_i,
                           const int*   __restrict__ edge_j)
{
    int e = blockIdx.x * blockDim.x + threadIdx.x;
    if (e >= N_EDGES) return;
    int i = edge_i[e], j = edge_j[e];
    float dx = node_pos[3*i+0] - node_pos[3*j+0];
    float dy = node_pos[3*i+1] - node_pos[3*j+1];
    float dz = node_pos[3*i+2] - node_pos[3*j+2];
    float d  = sqrtf(dx*dx + dy*dy + dz*dz);
    d = fmaxf(d, EPSF);
    float ds = d / CUTOFF;

    float r0=0.f,r1=0.f,r2=0.f,r3=0.f,r4=0.f,r5=0.f;
    if (ds <= 1.0f) {
        float th = PI_F * ds;
        float s, c;
        sincosf(th, &s, &c);
        float env = 0.5f * (c + 1.0f);
        float inv = env / fmaxf(ds, 1e-6f);
        // sin(n*th) via Chebyshev recurrence
        float c2 = 2.0f * c;
        float sm2 = 0.0f, sm1 = s;
        r0 = inv * sm1;
        float sn;
        sn = c2*sm1 - sm2; sm2 = sm1; sm1 = sn; r1 = inv * sn;
        sn = c2*sm1 - sm2; sm2 = sm1; sm1 = sn; r2 = inv * sn;
        sn = c2*sm1 - sm2; sm2 = sm1; sm1 = sn; r3 = inv * sn;
        sn = c2*sm1 - sm2; sm2 = sm1; sm1 = sn; r4 = inv * sn;
        sn = c2*sm1 - sm2; sm2 = sm1; sm1 = sn; r5 = inv * sn;
    }

    float4* row = (float4*)(g_feat + (size_t)e * FEAT);
    float4 z = make_float4(0.f, 0.f, 0.f, 0.f);
    #pragma unroll
    for (int q = 0; q < 10; q++) row[q] = z;           // words 0..39
    row[10] = make_float4(0.f, 0.f, r0, r1);           // words 40,41 (sbf tail), 42,43
    row[11] = make_float4(r2, r3, r4, r5);             // words 44..47
}

// ---------------------------------------------------------------------------
// Kernel 2: per-triplet angle -> cbf, outer with gathered rbf, atomic into
// the target edge's 42-float accumulator. Early-exit on zero rbf (~70%).
// ---------------------------------------------------------------------------
__global__ void triplet_kernel(const float* __restrict__ node_pos,
                               const float* __restrict__ group_pos,
                               const int* __restrict__ t_i,
                               const int* __restrict__ t_j,
                               const int* __restrict__ t_k,
                               const int* __restrict__ id_kj,
                               const int* __restrict__ id_ji)
{
    int t = blockIdx.x * blockDim.x + threadIdx.x;
    if (t >= N_TRIP) return;

    int kj = id_kj[t];
    const float* rrow = g_feat + (size_t)kj * FEAT + 42;
    float2 ra = *(const float2*)(rrow + 0);
    float2 rb2 = *(const float2*)(rrow + 2);
    float2 rc = *(const float2*)(rrow + 4);
    if (ra.x == 0.f && ra.y == 0.f && rb2.x == 0.f && rb2.y == 0.f &&
        rc.x == 0.f && rc.y == 0.f)
        return;  // rbf identically zero -> contributes exactly 0

    int ti = t_i[t], tj = t_j[t], tk = t_k[t];
    float gx = group_pos[3*ti+0], gy = group_pos[3*ti+1], gz = group_pos[3*ti+2];
    float ax = node_pos[3*tj+0] - gx, ay = node_pos[3*tj+1] - gy, az = node_pos[3*tj+2] - gz;
    float bx = node_pos[3*tk+0] - gx, by = node_pos[3*tk+1] - gy, bz = node_pos[3*tk+2] - gz;

    float n1 = sqrtf(ax*ax + ay*ay + az*az) + EPSF;
    float n2 = sqrtf(bx*bx + by*by + bz*bz) + EPSF;
    bool too_close = (n1 < 1e-4f) || (n2 < 1e-4f);
    float i1 = 1.0f / n1, i2 = 1.0f / n2;
    float ux = ax*i1, uy = ay*i1, uz = az*i1;
    float vx = bx*i2, vy = by*i2, vz = bz*i2;
    float x = ux*vx + uy*vy + uz*vz;
    x = fminf(fmaxf(x, -1.0f + EPSF), 1.0f - EPSF);
    float cx_ = uy*vz - uz*vy;
    float cy_ = uz*vx - ux*vz;
    float cz_ = ux*vy - uy*vx;
    float y = sqrtf(cx_*cx_ + cy_*cy_ + cz_*cz_);
    float ang = atan2f(y, x);
    if (too_close) ang = PI_F * 0.5f;
    ang = fminf(fmaxf(ang, EPSF), PI_F - EPSF);

    float c = cosf(ang);
    float c2 = c*c, c3 = c2*c, c4 = c2*c2, c5 = c3*c2;
    float cb[7];
    cb[0] = 0.282094791774f;
    cb[1] = 0.488602511903f * c;
    cb[2] = 0.630783130505f * (1.5f*c2 - 0.5f);
    cb[3] = 0.746352665180f * (2.5f*c3 - 1.5f*c);
    cb[4] = 0.846284375322f * (4.375f*c4 - 3.75f*c2 + 0.375f);
    cb[5] = 0.935602579627f * (7.875f*c5 - 8.75f*c3 + 1.875f*c);
    cb[6] = 1.017107236282f * cosf(6.0f * ang);

    float rb[6] = { ra.x, ra.y, rb2.x, rb2.y, rc.x, rc.y };

    int ji = id_ji[t];
    float* dst = g_feat + (size_t)ji * FEAT;
    #pragma unroll
    for (int q = 0; q < 10; q++) {
        int w = 4*q;
        float4 v = make_float4(cb[(w+0)/6] * rb[(w+0)%6],
                               cb[(w+1)/6] * rb[(w+1)%6],
                               cb[(w+2)/6] * rb[(w+2)%6],
                               cb[(w+3)/6] * rb[(w+3)%6]);
        atomicAdd((float4*)(dst + w), v);
    }
    float2 v2 = make_float2(cb[6]*rb[4], cb[6]*rb[5]);
    atomicAdd((float2*)(dst + 40), v2);
}

// ---------------------------------------------------------------------------
// Kernel 3: out[e][h] = b[h] + feat[e][0..41] @ W_sbf + feat[e][42..47] @ W_rbf
// W (48x128) staged in shared; warp processes 4 edges with 4x4 register tile.
// ---------------------------------------------------------------------------
__global__ void __launch_bounds__(128) out_kernel(
    const float* __restrict__ W_sbf,
    const float* __restrict__ W_rbf,
    const float* __restrict__ b_rbf,
    float* __restrict__ out)
{
    __shared__ float Wsh[FEAT * HID];
    __shared__ float bsh[HID];
    for (int i = threadIdx.x; i < 42 * HID; i += blockDim.x) Wsh[i] = W_sbf[i];
    for (int i = threadIdx.x; i < 6 * HID; i += blockDim.x)  Wsh[42*HID + i] = W_rbf[i];
    if (threadIdx.x < HID) bsh[threadIdx.x] = b_rbf[threadIdx.x];
    __syncthreads();

    int lane = threadIdx.x & 31;
    int warp = threadIdx.x >> 5;
    int gw   = blockIdx.x * 4 + warp;
    int nw   = gridDim.x * 4;
    int hb   = lane * 4;

    float b0 = bsh[hb], b1 = bsh[hb+1], b2 = bsh[hb+2], b3 = bsh[hb+3];

    for (int e0 = gw * 4; e0 < N_EDGES; e0 += nw * 4) {
        float acc[4][4];
        #pragma unroll
        for (int e = 0; e < 4; e++) {
            acc[e][0] = b0; acc[e][1] = b1; acc[e][2] = b2; acc[e][3] = b3;
        }
        #pragma unroll
        for (int chunk = 0; chunk < 12; chunk++) {
            float4 v[4];
            #pragma unroll
            for (int e = 0; e < 4; e++)
                v[e] = *(const float4*)(g_feat + (size_t)(e0+e) * FEAT + chunk*4);
            #pragma unroll
            for (int j = 0; j < 4; j++) {
                int k = chunk*4 + j;
                float4 w = *(const float4*)(Wsh + k*HID + hb);
                #pragma unroll
                for (int e = 0; e < 4; e++) {
                    float val = (j == 0) ? v[e].x : (j == 1) ? v[e].y
                              : (j == 2) ? v[e].z : v[e].w;
                    acc[e][0] = fmaf(val, w.x, acc[e][0]);
                    acc[e][1] = fmaf(val, w.y, acc[e][1]);
                    acc[e][2] = fmaf(val, w.z, acc[e][2]);
                    acc[e][3] = fmaf(val, w.w, acc[e][3]);
                }
            }
        }
        #pragma unroll
        for (int e = 0; e < 4; e++) {
            *(float4*)(out + (size_t)(e0+e) * HID + hb) =
                make_float4(acc[e][0], acc[e][1], acc[e][2], acc[e][3]);
        }
    }
}

// ---------------------------------------------------------------------------
extern "C" void kernel_launch(void* const* d_in, const int* in_sizes, int n_in,
                              void* d_out, int out_size)
{
    const float* node_pos  = (const float*)d_in[0];
    const float* group_pos = (const float*)d_in[1];
    // d_in[2] = edge_attr (unused by reference)
    const float* W_rbf     = (const float*)d_in[3];
    const float* b_rbf     = (const float*)d_in[4];
    const float* W_sbf     = (const float*)d_in[5];
    const int*   edge_i    = (const int*)d_in[6];
    const int*   edge_j    = (const int*)d_in[7];
    const int*   trip_i    = (const int*)d_in[8];
    const int*   trip_j    = (const int*)d_in[9];
    const int*   trip_k    = (const int*)d_in[10];
    const int*   id_kj     = (const int*)d_in[11];
    const int*   id_ji     = (const int*)d_in[12];
    float* out = (float*)d_out;

    rbf_kernel<<<(N_EDGES + 255)/256, 256>>>(node_pos, edge_i, edge_j);
    triplet_kernel<<<(N_TRIP + 255)/256, 256>>>(node_pos, group_pos,
                                                trip_i, trip_j, trip_k,
                                                id_kj, id_ji);
    out_kernel<<<1184, 128>>>(W_sbf, W_rbf, b_rbf, out);
}